// round 14
// baseline (speedup 1.0000x reference)
#include <cuda_runtime.h>
#include <cuda_bf16.h>
#include <cstdint>

typedef unsigned long long ull;

#define NSEQ 480
#define TLEN 200
#define CH   64
#define HID  128
#define G4   512
#define NROW (NSEQ * TLEN)   // 96000

// ---------------- device scratch ----------------
__device__ __nv_bfloat16 g_xh[NROW * CH];    // x hi split, [t*480+seq][c]
__device__ __nv_bfloat16 g_xl[NROW * CH];    // x lo split
__device__ __nv_bfloat16 g_Wh[G4 * CH];      // W_ih hi split, [g][c]
__device__ __nv_bfloat16 g_Wl[G4 * CH];      // W_ih lo split
__device__ __nv_bfloat16 g_WhhHi[G4 * HID];  // W_hh hi split, [g][k]
__device__ __nv_bfloat16 g_WhhLo[G4 * HID];  // W_hh lo split
__device__ float g_xg[NROW * G4];            // input gates [t*480+seq][g]
__device__ float g_bias[G4];

// ---------------- helpers ----------------
__device__ __forceinline__ float tanh_t(float x) {
    float t; asm("tanh.approx.f32 %0, %1;" : "=f"(t) : "f"(x)); return t;
}
__device__ __forceinline__ uint32_t smem_u32(const void* p) {
    uint32_t a;
    asm("{ .reg .u64 t; cvta.to.shared.u64 t, %1; cvt.u32.u64 %0, t; }" : "=r"(a) : "l"(p));
    return a;
}
__device__ __forceinline__ void mma16816(float* d, const uint32_t* a, uint32_t b0, uint32_t b1) {
    asm volatile(
        "mma.sync.aligned.m16n8k16.row.col.f32.bf16.bf16.f32 "
        "{%0,%1,%2,%3}, {%4,%5,%6,%7}, {%8,%9}, {%0,%1,%2,%3};"
        : "+f"(d[0]), "+f"(d[1]), "+f"(d[2]), "+f"(d[3])
        : "r"(a[0]), "r"(a[1]), "r"(a[2]), "r"(a[3]), "r"(b0), "r"(b1));
}
__device__ __forceinline__ void ldsm4(uint32_t* r, uint32_t addr) {
    asm volatile("ldmatrix.sync.aligned.m8n8.x4.shared.b16 {%0,%1,%2,%3}, [%4];"
        : "=r"(r[0]), "=r"(r[1]), "=r"(r[2]), "=r"(r[3]) : "r"(addr));
}

// ---------------- prep: bf16 splits + bias fold ----------------
__global__ void __launch_bounds__(256) prep_kernel(
    const float* __restrict__ Wih, const float* __restrict__ Whh,
    const float* __restrict__ bih, const float* __restrict__ bhh)
{
    int idx = blockIdx.x * 256 + threadIdx.x;
    if (idx < G4 * HID) {
        float w = Whh[idx];
        __nv_bfloat16 hi = __float2bfloat16(w);
        g_WhhHi[idx] = hi;
        g_WhhLo[idx] = __float2bfloat16(w - __bfloat162float(hi));
    }
    if (idx < G4 * CH) {
        float w = Wih[idx];
        __nv_bfloat16 hi = __float2bfloat16(w);
        g_Wh[idx] = hi;
        g_Wl[idx] = __float2bfloat16(w - __bfloat162float(hi));
    }
    if (idx < G4) g_bias[idx] = bih[idx] + bhh[idx];
}

// ---------------- transpose + bf16 split ----------------
__global__ void __launch_bounds__(256) transp_kernel(const float* __restrict__ x)
{
    __shared__ float tile[64 * 30];
    int t = blockIdx.x, b = blockIdx.y;
    for (int idx = threadIdx.x; idx < 64 * 30; idx += 256) {
        int c = idx / 30, p = idx - c * 30;
        tile[idx] = x[(b * 64 + c) * 6000 + t * 30 + p];
    }
    __syncthreads();
    for (int idx = threadIdx.x; idx < 64 * 30; idx += 256) {
        int p = idx >> 6, c = idx & 63;
        float v = tile[c * 30 + p];
        __nv_bfloat16 hi = __float2bfloat16(v);
        int o = (t * NSEQ + b * 30 + p) * 64 + c;
        g_xh[o] = hi;
        g_xl[o] = __float2bfloat16(v - __bfloat162float(hi));
    }
}

// ---------------- HMMA GEMM: xg = split3(x @ Wih^T) + bias (R9, unchanged) ----------------
#define HG_B0   36864
#define HG_BIAS 73728
#define HG_SMEM 74240

__global__ void __launch_bounds__(256) hgemm_kernel()
{
    extern __shared__ char sm[];
    int tid = threadIdx.x, w = tid >> 5, l = tid & 31;
    int row0 = blockIdx.x * 128, col0 = blockIdx.y * 128;

    for (int i = tid; i < 4096; i += 256) {
        int isB = i >> 11;
        int j = i & 2047;
        int arr = j >> 10, rem = j & 1023, row = rem >> 3, ch = rem & 7;
        const uint4* src;
        size_t gidx;
        if (!isB) {
            src = arr ? (const uint4*)g_xl : (const uint4*)g_xh;
            gidx = (size_t)(row0 + row) * 8 + ch;
        } else {
            src = arr ? (const uint4*)g_Wl : (const uint4*)g_Wh;
            gidx = (size_t)(col0 + row) * 8 + ch;
        }
        *(uint4*)(sm + isB * 36864 + arr * 18432 + row * 144 + ch * 16) = src[gidx];
    }
    if (tid < 128) ((float*)(sm + HG_BIAS))[tid] = g_bias[col0 + tid];
    __syncthreads();

    int lr = l >> 2;
    int lc = (l & 3) * 2;

    float acc[16][4];
#pragma unroll
    for (int nf = 0; nf < 16; nf++)
#pragma unroll
        for (int j = 0; j < 4; j++) acc[nf][j] = 0.f;

#pragma unroll
    for (int kf = 0; kf < 4; kf++) {
        int aoff = (w * 16 + lr) * 144 + (kf * 16 + lc) * 2;
        uint32_t ah[4], al[4];
        ah[0] = *(const uint32_t*)(sm + aoff);
        ah[1] = *(const uint32_t*)(sm + aoff + 8 * 144);
        ah[2] = *(const uint32_t*)(sm + aoff + 16);
        ah[3] = *(const uint32_t*)(sm + aoff + 8 * 144 + 16);
        al[0] = *(const uint32_t*)(sm + 18432 + aoff);
        al[1] = *(const uint32_t*)(sm + 18432 + aoff + 8 * 144);
        al[2] = *(const uint32_t*)(sm + 18432 + aoff + 16);
        al[3] = *(const uint32_t*)(sm + 18432 + aoff + 8 * 144 + 16);
#pragma unroll
        for (int nf = 0; nf < 16; nf++) {
            int boff = HG_B0 + (nf * 8 + lr) * 144 + (kf * 16 + lc) * 2;
            uint32_t bh0 = *(const uint32_t*)(sm + boff);
            uint32_t bh1 = *(const uint32_t*)(sm + boff + 16);
            uint32_t bl0 = *(const uint32_t*)(sm + boff + 18432);
            uint32_t bl1 = *(const uint32_t*)(sm + boff + 18432 + 16);
            mma16816(acc[nf], ah, bh0, bh1);
            mma16816(acc[nf], al, bh0, bh1);
            mma16816(acc[nf], ah, bl0, bl1);
        }
    }

    const float* bs = (const float*)(sm + HG_BIAS);
    int rgA = row0 + w * 16 + lr;
#pragma unroll
    for (int nf = 0; nf < 16; nf++) {
        float b0 = bs[nf * 8 + lc], b1 = bs[nf * 8 + lc + 1];
        size_t cA = (size_t)rgA * 512 + col0 + nf * 8 + lc;
        *(float2*)&g_xg[cA] = make_float2(acc[nf][0] + b0, acc[nf][1] + b1);
        *(float2*)&g_xg[cA + 8 * 512] = make_float2(acc[nf][2] + b0, acc[nf][3] + b1);
    }
}

// ---------------- persistent LSTM: combined-B HMMA, pipelined kf loop ----------------
// lstm4 structure (8 warps, 1 bar/step, combined-B) with explicit kf software
// pipeline: next kf's B loads + ldmatrix issued before current kf's mma block.
// smem:
#define L4_WLO 0                       // WhhLo padded: 512 rows x 272 B = 139264
#define L4_XB  139264                  // xg double buf: 2 x 4x520 floats = 16640
#define L4_HB  155904                  // B double buf: 2 x 8 cols x 272 B = 4352
#define L4_HF  160256                  // h fp32 [128][4] = 2048
#define L4_TOTAL 162304

__global__ void __launch_bounds__(256) lstm6_kernel(
    const float* __restrict__ Wfc, const float* __restrict__ bfc,
    float* __restrict__ out)
{
    extern __shared__ char sm[];
    int tid = threadIdx.x, w = tid >> 5, l = tid & 31;
    int s0 = blockIdx.x * 4;
    uint32_t smb = smem_u32(sm);

    // stage WhhLo into 272-B padded rows
    {
        const uint32_t* wlo = (const uint32_t*)g_WhhLo;  // [512][64] u32
        for (int i = tid; i < 512 * 64; i += 256) {
            int row = i >> 6, cp = i & 63;
            *(uint32_t*)(sm + L4_WLO + row * 272 + cp * 4) = wlo[row * 64 + cp];
        }
    }
    // zero h (B) buffers
    for (int i = tid; i < 4352 / 4; i += 256) ((uint32_t*)(sm + L4_HB))[i] = 0;
    // preload xb t=0 (buffer 0)
    const float4* xg4 = (const float4*)g_xg;
    for (int i = tid; i < 512; i += 256) {
        int s = i >> 7, g4i = i & 127;
        *(float4*)(sm + L4_XB + (s * 520 + g4i * 4) * 4) = xg4[(size_t)(s0 + s) * 128 + g4i];
    }

    // WhhHi fragments -> registers: WH[gate][kf][4], rows gate*128 + w*16
    uint32_t WH[4][8][4];
    {
        const uint32_t* whi = (const uint32_t*)g_WhhHi;  // [512][64] u32
        int lr = l >> 2, lc = l & 3;
#pragma unroll
        for (int mf = 0; mf < 4; mf++)
#pragma unroll
            for (int kf = 0; kf < 8; kf++) {
                int row = mf * 128 + w * 16 + lr;
                int kc = kf * 8 + lc;
                WH[mf][kf][0] = whi[row * 64 + kc];
                WH[mf][kf][1] = whi[(row + 8) * 64 + kc];
                WH[mf][kf][2] = whi[row * 64 + kc + 4];
                WH[mf][kf][3] = whi[(row + 8) * 64 + kc + 4];
            }
    }
    __syncthreads();

    // ldmatrix lane base for WhhLo A-frags (mf stride 128*272)
    int lm = l >> 3, lr8 = l & 7;
    uint32_t wloBase = smb + L4_WLO
        + (uint32_t)((w * 16 + (lm & 1) * 8 + lr8) * 272 + ((lm >> 1) * 8) * 2);

    // register-resident Wlo for mf=0
    uint32_t WL0[8][4];
#pragma unroll
    for (int kf = 0; kf < 8; kf++) ldsm4(WL0[kf], wloBase + kf * 32);

    // B-frag lane base (buffer 0)
    uint32_t hbA = smb + L4_HB + (uint32_t)((l >> 2) * 272 + (l & 3) * 4);

    // xb prefetch mapping
    int rC = tid & 127, sB = tid >> 7;

    // cell ownership: each lane owns (rL, sL) and (rL, sL+1)
    bool Alane = (l & 3) < 2;
    int rL = w * 16 + (l >> 2) + (Alane ? 0 : 8);
    int sL = ((l & 3) & 1) * 2;
    float cs0 = 0.f, cs1 = 0.f;

#pragma unroll 1
    for (int t = 0; t < TLEN; t++) {
        bool pf = (t + 1 < TLEN);
        float4 nx0, nx1;
        if (pf) {
            nx0 = xg4[(size_t)((t + 1) * NSEQ + s0 + sB) * 128 + rC];
            nx1 = xg4[(size_t)((t + 1) * NSEQ + s0 + sB + 2) * 128 + rC];
        }

        uint32_t hcur = hbA + (t & 1) * 2176;
        float acc[4][4];
#pragma unroll
        for (int mf = 0; mf < 4; mf++) {
            acc[mf][0] = 0.f; acc[mf][1] = 0.f; acc[mf][2] = 0.f; acc[mf][3] = 0.f;
        }

        // ---- software-pipelined kf loop ----
        uint32_t bh0, bh1;
        uint32_t wl[3][4];
        // prologue: load kf=0 fragments
        asm volatile("ld.shared.b32 %0, [%1];" : "=r"(bh0) : "r"(hcur));
        asm volatile("ld.shared.b32 %0, [%1];" : "=r"(bh1) : "r"(hcur + 16));
        ldsm4(wl[0], wloBase + 1 * (128 * 272));
        ldsm4(wl[1], wloBase + 2 * (128 * 272));
        ldsm4(wl[2], wloBase + 3 * (128 * 272));

#pragma unroll
        for (int kf = 0; kf < 8; kf++) {
            uint32_t nbh0, nbh1, nwl[3][4];
            if (kf < 7) {
                uint32_t ka = hcur + (kf + 1) * 32;
                asm volatile("ld.shared.b32 %0, [%1];" : "=r"(nbh0) : "r"(ka));
                asm volatile("ld.shared.b32 %0, [%1];" : "=r"(nbh1) : "r"(ka + 16));
                ldsm4(nwl[0], wloBase + 1 * (128 * 272) + (kf + 1) * 32);
                ldsm4(nwl[1], wloBase + 2 * (128 * 272) + (kf + 1) * 32);
                ldsm4(nwl[2], wloBase + 3 * (128 * 272) + (kf + 1) * 32);
            }
            // mma with current fragments
            mma16816(acc[0], WH[0][kf], bh0, bh1);
            mma16816(acc[0], WL0[kf], bh0, bh1);
            mma16816(acc[1], WH[1][kf], bh0, bh1);
            mma16816(acc[1], wl[0], bh0, bh1);
            mma16816(acc[2], WH[2][kf], bh0, bh1);
            mma16816(acc[2], wl[1], bh0, bh1);
            mma16816(acc[3], WH[3][kf], bh0, bh1);
            mma16816(acc[3], wl[2], bh0, bh1);
            if (kf < 7) {
                bh0 = nbh0; bh1 = nbh1;
#pragma unroll
                for (int m = 0; m < 3; m++) {
                    wl[m][0] = nwl[m][0]; wl[m][1] = nwl[m][1];
                    wl[m][2] = nwl[m][2]; wl[m][3] = nwl[m][3];
                }
            }
        }

        // store next xb buffer
        if (pf) {
            float* xd = (float*)(sm + L4_XB + ((t + 1) & 1) * 8320);
            *(float4*)&xd[sB * 520 + rC * 4] = nx0;
            *(float4*)&xd[(sB + 2) * 520 + rC * 4] = nx1;
        }

        // half-column sums via shfl_xor(2): lane gets its 2 complete cells
        float g0[4], g1[4];
#pragma unroll
        for (int mf = 0; mf < 4; mf++) {
            float sa = Alane ? acc[mf][2] : acc[mf][0];
            float ra = __shfl_xor_sync(0xffffffffu, sa, 2);
            float sb2 = Alane ? acc[mf][3] : acc[mf][1];
            float rb = __shfl_xor_sync(0xffffffffu, sb2, 2);
            g0[mf] = (Alane ? acc[mf][0] : acc[mf][2]) + ra;
            g1[mf] = (Alane ? acc[mf][1] : acc[mf][3]) + rb;
        }

        // activations: 2 cells per lane
        {
            const float* xbc = (const float*)(sm + L4_XB + (t & 1) * 8320);
            char* hn = sm + L4_HB + ((t + 1) & 1) * 2176;
            float* hf = (float*)(sm + L4_HF);

            // cell 0: (rL, sL)
            {
                float gi = g0[0] + xbc[sL * 520 + rL];
                float gf = g0[1] + xbc[sL * 520 + 128 + rL];
                float gg = g0[2] + xbc[sL * 520 + 256 + rL];
                float go = g0[3] + xbc[sL * 520 + 384 + rL];
                float i_ = 0.5f * tanh_t(0.5f * gi) + 0.5f;
                float f_ = 0.5f * tanh_t(0.5f * gf) + 0.5f;
                float o_ = 0.5f * tanh_t(0.5f * go) + 0.5f;
                float g_ = tanh_t(gg);
                cs0 = f_ * cs0 + i_ * g_;
                float h = o_ * tanh_t(cs0);
                __nv_bfloat16 hi = __float2bfloat16(h);
                float lo = h - __bfloat162float(hi);
                *(__nv_bfloat16*)(hn + sL * 272 + rL * 2) = hi;
                *(__nv_bfloat16*)(hn + (4 + sL) * 272 + rL * 2) = __float2bfloat16(lo);
                if (t == TLEN - 1) hf[rL * 4 + sL] = h;
            }
            // cell 1: (rL, sL+1)
            {
                int s1 = sL + 1;
                float gi = g1[0] + xbc[s1 * 520 + rL];
                float gf = g1[1] + xbc[s1 * 520 + 128 + rL];
                float gg = g1[2] + xbc[s1 * 520 + 256 + rL];
                float go = g1[3] + xbc[s1 * 520 + 384 + rL];
                float i_ = 0.5f * tanh_t(0.5f * gi) + 0.5f;
                float f_ = 0.5f * tanh_t(0.5f * gf) + 0.5f;
                float o_ = 0.5f * tanh_t(0.5f * go) + 0.5f;
                float g_ = tanh_t(gg);
                cs1 = f_ * cs1 + i_ * g_;
                float h = o_ * tanh_t(cs1);
                __nv_bfloat16 hi = __float2bfloat16(h);
                float lo = h - __bfloat162float(hi);
                *(__nv_bfloat16*)(hn + s1 * 272 + rL * 2) = hi;
                *(__nv_bfloat16*)(hn + (4 + s1) * 272 + rL * 2) = __float2bfloat16(lo);
                if (t == TLEN - 1) hf[rL * 4 + s1] = h;
            }
        }
        __syncthreads();
    }

    // ---- FC epilogue: reuse WLO region for W_fc^T ----
    float* wfs = (float*)sm;
    for (int idx = tid; idx < CH * HID; idx += 256) {
        int c = idx >> 7, j = idx & 127;
        wfs[j * 64 + c] = Wfc[idx];
    }
    __syncthreads();
    {
        int c = tid & 63, s = tid >> 6;
        float accf = bfc[c];
        const float* hf = (const float*)(sm + L4_HF);
#pragma unroll 8
        for (int j = 0; j < HID; j++)
            accf += hf[j * 4 + s] * wfs[j * 64 + c];
        out[(s0 + s) * 64 + c] = accf;
    }
}

// ---------------- launch ----------------
extern "C" void kernel_launch(void* const* d_in, const int* in_sizes, int n_in,
                              void* d_out, int out_size)
{
    const float* x   = (const float*)d_in[0];
    const float* Wih = (const float*)d_in[1];
    const float* Whh = (const float*)d_in[2];
    const float* bih = (const float*)d_in[3];
    const float* bhh = (const float*)d_in[4];
    const float* Wfc = (const float*)d_in[5];
    const float* bfc = (const float*)d_in[6];
    float* out = (float*)d_out;

    cudaFuncSetAttribute(hgemm_kernel, cudaFuncAttributeMaxDynamicSharedMemorySize, HG_SMEM);
    cudaFuncSetAttribute(lstm6_kernel, cudaFuncAttributeMaxDynamicSharedMemorySize, L4_TOTAL);

    prep_kernel<<<256, 256>>>(Wih, Whh, bih, bhh);
    transp_kernel<<<dim3(TLEN, 16), 256>>>(x);
    hgemm_kernel<<<dim3(NROW / 128, 4), 256, HG_SMEM>>>();
    lstm6_kernel<<<120, 256, L4_TOTAL>>>(Wfc, bfc, out);
}

// round 15
// speedup vs baseline: 1.1004x; 1.1004x over previous
#include <cuda_runtime.h>
#include <cuda_bf16.h>
#include <cstdint>

typedef unsigned long long ull;

#define NSEQ 480
#define TLEN 200
#define CH   64
#define HID  128
#define G4   512
#define NROW (NSEQ * TLEN)   // 96000

// ---------------- device scratch ----------------
__device__ __nv_bfloat16 g_xh[NROW * CH];    // x hi split, [t*480+seq][c]
__device__ __nv_bfloat16 g_xl[NROW * CH];    // x lo split
__device__ __nv_bfloat16 g_Wh[G4 * CH];      // W_ih hi split, [g][c]
__device__ __nv_bfloat16 g_Wl[G4 * CH];      // W_ih lo split
__device__ __nv_bfloat16 g_WhhHi[G4 * HID];  // W_hh hi split, [g][k]
__device__ __nv_bfloat16 g_WhhLo[G4 * HID];  // W_hh lo split
__device__ float g_xg[NROW * G4];            // input gates [t*480+seq][g]
__device__ float g_bias[G4];

// ---------------- helpers ----------------
__device__ __forceinline__ float tanh_t(float x) {
    float t; asm("tanh.approx.f32 %0, %1;" : "=f"(t) : "f"(x)); return t;
}
__device__ __forceinline__ uint32_t smem_u32(const void* p) {
    uint32_t a;
    asm("{ .reg .u64 t; cvta.to.shared.u64 t, %1; cvt.u32.u64 %0, t; }" : "=r"(a) : "l"(p));
    return a;
}
__device__ __forceinline__ void mma16816(float* d, const uint32_t* a, uint32_t b0, uint32_t b1) {
    asm volatile(
        "mma.sync.aligned.m16n8k16.row.col.f32.bf16.bf16.f32 "
        "{%0,%1,%2,%3}, {%4,%5,%6,%7}, {%8,%9}, {%0,%1,%2,%3};"
        : "+f"(d[0]), "+f"(d[1]), "+f"(d[2]), "+f"(d[3])
        : "r"(a[0]), "r"(a[1]), "r"(a[2]), "r"(a[3]), "r"(b0), "r"(b1));
}
__device__ __forceinline__ void ldsm4(uint32_t* r, uint32_t addr) {
    asm volatile("ldmatrix.sync.aligned.m8n8.x4.shared.b16 {%0,%1,%2,%3}, [%4];"
        : "=r"(r[0]), "=r"(r[1]), "=r"(r[2]), "=r"(r[3]) : "r"(addr));
}

// ---------------- prep: bf16 splits + bias fold ----------------
__global__ void __launch_bounds__(256) prep_kernel(
    const float* __restrict__ Wih, const float* __restrict__ Whh,
    const float* __restrict__ bih, const float* __restrict__ bhh)
{
    int idx = blockIdx.x * 256 + threadIdx.x;
    if (idx < G4 * HID) {
        float w = Whh[idx];
        __nv_bfloat16 hi = __float2bfloat16(w);
        g_WhhHi[idx] = hi;
        g_WhhLo[idx] = __float2bfloat16(w - __bfloat162float(hi));
    }
    if (idx < G4 * CH) {
        float w = Wih[idx];
        __nv_bfloat16 hi = __float2bfloat16(w);
        g_Wh[idx] = hi;
        g_Wl[idx] = __float2bfloat16(w - __bfloat162float(hi));
    }
    if (idx < G4) g_bias[idx] = bih[idx] + bhh[idx];
}

// ---------------- transpose + bf16 split ----------------
__global__ void __launch_bounds__(256) transp_kernel(const float* __restrict__ x)
{
    __shared__ float tile[64 * 30];
    int t = blockIdx.x, b = blockIdx.y;
    for (int idx = threadIdx.x; idx < 64 * 30; idx += 256) {
        int c = idx / 30, p = idx - c * 30;
        tile[idx] = x[(b * 64 + c) * 6000 + t * 30 + p];
    }
    __syncthreads();
    for (int idx = threadIdx.x; idx < 64 * 30; idx += 256) {
        int p = idx >> 6, c = idx & 63;
        float v = tile[c * 30 + p];
        __nv_bfloat16 hi = __float2bfloat16(v);
        int o = (t * NSEQ + b * 30 + p) * 64 + c;
        g_xh[o] = hi;
        g_xl[o] = __float2bfloat16(v - __bfloat162float(hi));
    }
}

// ---------------- HMMA GEMM: xg = split3(x @ Wih^T) + bias (R9, unchanged) ----------------
#define HG_B0   36864
#define HG_BIAS 73728
#define HG_SMEM 74240

__global__ void __launch_bounds__(256) hgemm_kernel()
{
    extern __shared__ char sm[];
    int tid = threadIdx.x, w = tid >> 5, l = tid & 31;
    int row0 = blockIdx.x * 128, col0 = blockIdx.y * 128;

    for (int i = tid; i < 4096; i += 256) {
        int isB = i >> 11;
        int j = i & 2047;
        int arr = j >> 10, rem = j & 1023, row = rem >> 3, ch = rem & 7;
        const uint4* src;
        size_t gidx;
        if (!isB) {
            src = arr ? (const uint4*)g_xl : (const uint4*)g_xh;
            gidx = (size_t)(row0 + row) * 8 + ch;
        } else {
            src = arr ? (const uint4*)g_Wl : (const uint4*)g_Wh;
            gidx = (size_t)(col0 + row) * 8 + ch;
        }
        *(uint4*)(sm + isB * 36864 + arr * 18432 + row * 144 + ch * 16) = src[gidx];
    }
    if (tid < 128) ((float*)(sm + HG_BIAS))[tid] = g_bias[col0 + tid];
    __syncthreads();

    int lr = l >> 2;
    int lc = (l & 3) * 2;

    float acc[16][4];
#pragma unroll
    for (int nf = 0; nf < 16; nf++)
#pragma unroll
        for (int j = 0; j < 4; j++) acc[nf][j] = 0.f;

#pragma unroll
    for (int kf = 0; kf < 4; kf++) {
        int aoff = (w * 16 + lr) * 144 + (kf * 16 + lc) * 2;
        uint32_t ah[4], al[4];
        ah[0] = *(const uint32_t*)(sm + aoff);
        ah[1] = *(const uint32_t*)(sm + aoff + 8 * 144);
        ah[2] = *(const uint32_t*)(sm + aoff + 16);
        ah[3] = *(const uint32_t*)(sm + aoff + 8 * 144 + 16);
        al[0] = *(const uint32_t*)(sm + 18432 + aoff);
        al[1] = *(const uint32_t*)(sm + 18432 + aoff + 8 * 144);
        al[2] = *(const uint32_t*)(sm + 18432 + aoff + 16);
        al[3] = *(const uint32_t*)(sm + 18432 + aoff + 8 * 144 + 16);
#pragma unroll
        for (int nf = 0; nf < 16; nf++) {
            int boff = HG_B0 + (nf * 8 + lr) * 144 + (kf * 16 + lc) * 2;
            uint32_t bh0 = *(const uint32_t*)(sm + boff);
            uint32_t bh1 = *(const uint32_t*)(sm + boff + 16);
            uint32_t bl0 = *(const uint32_t*)(sm + boff + 18432);
            uint32_t bl1 = *(const uint32_t*)(sm + boff + 18432 + 16);
            mma16816(acc[nf], ah, bh0, bh1);
            mma16816(acc[nf], al, bh0, bh1);
            mma16816(acc[nf], ah, bl0, bl1);
        }
    }

    const float* bs = (const float*)(sm + HG_BIAS);
    int rgA = row0 + w * 16 + lr;
#pragma unroll
    for (int nf = 0; nf < 16; nf++) {
        float b0 = bs[nf * 8 + lc], b1 = bs[nf * 8 + lc + 1];
        size_t cA = (size_t)rgA * 512 + col0 + nf * 8 + lc;
        *(float2*)&g_xg[cA] = make_float2(acc[nf][0] + b0, acc[nf][1] + b1);
        *(float2*)&g_xg[cA + 8 * 512] = make_float2(acc[nf][2] + b0, acc[nf][3] + b1);
    }
}

// ---------------- persistent LSTM: combined-B HMMA, split accumulators ----------------
// lstm4 (R12 best) with ONE change: Whi-products and Wlo-products accumulate
// into separate accH/accL (8-deep chains instead of 16), summed after the loop.
// smem:
#define L4_WLO 0                       // WhhLo padded: 512 rows x 272 B = 139264
#define L4_XB  139264                  // xg double buf: 2 x 4x520 floats = 16640
#define L4_HB  155904                  // B double buf: 2 x 8 cols x 272 B = 4352
#define L4_HF  160256                  // h fp32 [128][4] = 2048
#define L4_TOTAL 162304

__global__ void __launch_bounds__(256) lstm7_kernel(
    const float* __restrict__ Wfc, const float* __restrict__ bfc,
    float* __restrict__ out)
{
    extern __shared__ char sm[];
    int tid = threadIdx.x, w = tid >> 5, l = tid & 31;
    int s0 = blockIdx.x * 4;
    uint32_t smb = smem_u32(sm);

    // stage WhhLo into 272-B padded rows
    {
        const uint32_t* wlo = (const uint32_t*)g_WhhLo;  // [512][64] u32
        for (int i = tid; i < 512 * 64; i += 256) {
            int row = i >> 6, cp = i & 63;
            *(uint32_t*)(sm + L4_WLO + row * 272 + cp * 4) = wlo[row * 64 + cp];
        }
    }
    // zero h (B) buffers
    for (int i = tid; i < 4352 / 4; i += 256) ((uint32_t*)(sm + L4_HB))[i] = 0;
    // preload xb t=0 (buffer 0)
    const float4* xg4 = (const float4*)g_xg;
    for (int i = tid; i < 512; i += 256) {
        int s = i >> 7, g4i = i & 127;
        *(float4*)(sm + L4_XB + (s * 520 + g4i * 4) * 4) = xg4[(size_t)(s0 + s) * 128 + g4i];
    }

    // WhhHi fragments -> registers: WH[gate][kf][4], rows gate*128 + w*16
    uint32_t WH[4][8][4];
    {
        const uint32_t* whi = (const uint32_t*)g_WhhHi;  // [512][64] u32
        int lr = l >> 2, lc = l & 3;
#pragma unroll
        for (int mf = 0; mf < 4; mf++)
#pragma unroll
            for (int kf = 0; kf < 8; kf++) {
                int row = mf * 128 + w * 16 + lr;
                int kc = kf * 8 + lc;
                WH[mf][kf][0] = whi[row * 64 + kc];
                WH[mf][kf][1] = whi[(row + 8) * 64 + kc];
                WH[mf][kf][2] = whi[row * 64 + kc + 4];
                WH[mf][kf][3] = whi[(row + 8) * 64 + kc + 4];
            }
    }
    __syncthreads();

    // ldmatrix lane base for WhhLo A-frags (mf stride 128*272)
    int lm = l >> 3, lr8 = l & 7;
    uint32_t wloBase = smb + L4_WLO
        + (uint32_t)((w * 16 + (lm & 1) * 8 + lr8) * 272 + ((lm >> 1) * 8) * 2);

    // register-resident Wlo for mf=0
    uint32_t WL0[8][4];
#pragma unroll
    for (int kf = 0; kf < 8; kf++) ldsm4(WL0[kf], wloBase + kf * 32);

    // B-frag lane base (buffer 0)
    uint32_t hbA = smb + L4_HB + (uint32_t)((l >> 2) * 272 + (l & 3) * 4);

    // xb prefetch mapping
    int rC = tid & 127, sB = tid >> 7;

    // cell ownership: each lane owns (rL, sL) and (rL, sL+1)
    bool Alane = (l & 3) < 2;
    int rL = w * 16 + (l >> 2) + (Alane ? 0 : 8);
    int sL = ((l & 3) & 1) * 2;
    float cs0 = 0.f, cs1 = 0.f;

#pragma unroll 1
    for (int t = 0; t < TLEN; t++) {
        bool pf = (t + 1 < TLEN);
        float4 nx0, nx1;
        if (pf) {
            nx0 = xg4[(size_t)((t + 1) * NSEQ + s0 + sB) * 128 + rC];
            nx1 = xg4[(size_t)((t + 1) * NSEQ + s0 + sB + 2) * 128 + rC];
        }

        uint32_t hcur = hbA + (t & 1) * 2176;
        float accH[4][4], accL[4][4];
#pragma unroll
        for (int mf = 0; mf < 4; mf++) {
#pragma unroll
            for (int j = 0; j < 4; j++) { accH[mf][j] = 0.f; accL[mf][j] = 0.f; }
        }

#pragma unroll
        for (int kf = 0; kf < 8; kf++) {
            uint32_t bh0, bh1;
            uint32_t ka = hcur + kf * 32;
            asm volatile("ld.shared.b32 %0, [%1];" : "=r"(bh0) : "r"(ka));
            asm volatile("ld.shared.b32 %0, [%1];" : "=r"(bh1) : "r"(ka + 16));
            // mf = 0: both W halves in registers
            mma16816(accH[0], WH[0][kf], bh0, bh1);
            mma16816(accL[0], WL0[kf], bh0, bh1);
#pragma unroll
            for (int mf = 1; mf < 4; mf++) {
                uint32_t wl[4];
                ldsm4(wl, wloBase + mf * (128 * 272) + kf * 32);
                mma16816(accH[mf], WH[mf][kf], bh0, bh1);
                mma16816(accL[mf], wl, bh0, bh1);
            }
        }

        // store next xb buffer
        if (pf) {
            float* xd = (float*)(sm + L4_XB + ((t + 1) & 1) * 8320);
            *(float4*)&xd[sB * 520 + rC * 4] = nx0;
            *(float4*)&xd[(sB + 2) * 520 + rC * 4] = nx1;
        }

        // combine split accumulators, then half-column sums via shfl_xor(2)
        float g0[4], g1[4];
#pragma unroll
        for (int mf = 0; mf < 4; mf++) {
            float a0 = accH[mf][0] + accL[mf][0];
            float a1 = accH[mf][1] + accL[mf][1];
            float a2 = accH[mf][2] + accL[mf][2];
            float a3 = accH[mf][3] + accL[mf][3];
            float sa = Alane ? a2 : a0;
            float ra = __shfl_xor_sync(0xffffffffu, sa, 2);
            float sb2 = Alane ? a3 : a1;
            float rb = __shfl_xor_sync(0xffffffffu, sb2, 2);
            g0[mf] = (Alane ? a0 : a2) + ra;
            g1[mf] = (Alane ? a1 : a3) + rb;
        }

        // activations: 2 cells per lane
        {
            const float* xbc = (const float*)(sm + L4_XB + (t & 1) * 8320);
            char* hn = sm + L4_HB + ((t + 1) & 1) * 2176;
            float* hf = (float*)(sm + L4_HF);

            // cell 0: (rL, sL)
            {
                float gi = g0[0] + xbc[sL * 520 + rL];
                float gf = g0[1] + xbc[sL * 520 + 128 + rL];
                float gg = g0[2] + xbc[sL * 520 + 256 + rL];
                float go = g0[3] + xbc[sL * 520 + 384 + rL];
                float i_ = 0.5f * tanh_t(0.5f * gi) + 0.5f;
                float f_ = 0.5f * tanh_t(0.5f * gf) + 0.5f;
                float o_ = 0.5f * tanh_t(0.5f * go) + 0.5f;
                float g_ = tanh_t(gg);
                cs0 = f_ * cs0 + i_ * g_;
                float h = o_ * tanh_t(cs0);
                __nv_bfloat16 hi = __float2bfloat16(h);
                float lo = h - __bfloat162float(hi);
                *(__nv_bfloat16*)(hn + sL * 272 + rL * 2) = hi;
                *(__nv_bfloat16*)(hn + (4 + sL) * 272 + rL * 2) = __float2bfloat16(lo);
                if (t == TLEN - 1) hf[rL * 4 + sL] = h;
            }
            // cell 1: (rL, sL+1)
            {
                int s1 = sL + 1;
                float gi = g1[0] + xbc[s1 * 520 + rL];
                float gf = g1[1] + xbc[s1 * 520 + 128 + rL];
                float gg = g1[2] + xbc[s1 * 520 + 256 + rL];
                float go = g1[3] + xbc[s1 * 520 + 384 + rL];
                float i_ = 0.5f * tanh_t(0.5f * gi) + 0.5f;
                float f_ = 0.5f * tanh_t(0.5f * gf) + 0.5f;
                float o_ = 0.5f * tanh_t(0.5f * go) + 0.5f;
                float g_ = tanh_t(gg);
                cs1 = f_ * cs1 + i_ * g_;
                float h = o_ * tanh_t(cs1);
                __nv_bfloat16 hi = __float2bfloat16(h);
                float lo = h - __bfloat162float(hi);
                *(__nv_bfloat16*)(hn + s1 * 272 + rL * 2) = hi;
                *(__nv_bfloat16*)(hn + (4 + s1) * 272 + rL * 2) = __float2bfloat16(lo);
                if (t == TLEN - 1) hf[rL * 4 + s1] = h;
            }
        }
        __syncthreads();
    }

    // ---- FC epilogue: reuse WLO region for W_fc^T ----
    float* wfs = (float*)sm;
    for (int idx = tid; idx < CH * HID; idx += 256) {
        int c = idx >> 7, j = idx & 127;
        wfs[j * 64 + c] = Wfc[idx];
    }
    __syncthreads();
    {
        int c = tid & 63, s = tid >> 6;
        float accf = bfc[c];
        const float* hf = (const float*)(sm + L4_HF);
#pragma unroll 8
        for (int j = 0; j < HID; j++)
            accf += hf[j * 4 + s] * wfs[j * 64 + c];
        out[(s0 + s) * 64 + c] = accf;
    }
}

// ---------------- launch ----------------
extern "C" void kernel_launch(void* const* d_in, const int* in_sizes, int n_in,
                              void* d_out, int out_size)
{
    const float* x   = (const float*)d_in[0];
    const float* Wih = (const float*)d_in[1];
    const float* Whh = (const float*)d_in[2];
    const float* bih = (const float*)d_in[3];
    const float* bhh = (const float*)d_in[4];
    const float* Wfc = (const float*)d_in[5];
    const float* bfc = (const float*)d_in[6];
    float* out = (float*)d_out;

    cudaFuncSetAttribute(hgemm_kernel, cudaFuncAttributeMaxDynamicSharedMemorySize, HG_SMEM);
    cudaFuncSetAttribute(lstm7_kernel, cudaFuncAttributeMaxDynamicSharedMemorySize, L4_TOTAL);

    prep_kernel<<<256, 256>>>(Wih, Whh, bih, bhh);
    transp_kernel<<<dim3(TLEN, 16), 256>>>(x);
    hgemm_kernel<<<dim3(NROW / 128, 4), 256, HG_SMEM>>>();
    lstm7_kernel<<<120, 256, L4_TOTAL>>>(Wfc, bfc, out);
}

// round 16
// speedup vs baseline: 1.2686x; 1.1529x over previous
#include <cuda_runtime.h>
#include <cuda_bf16.h>
#include <cstdint>

typedef unsigned long long ull;

#define NSEQ 480
#define TLEN 200
#define CH   64
#define HID  128
#define G4   512
#define NROW (NSEQ * TLEN)   // 96000

// ---------------- device scratch ----------------
__device__ __nv_bfloat16 g_xh[NROW * CH];    // x hi split, [t*480+seq][c]
__device__ __nv_bfloat16 g_xl[NROW * CH];    // x lo split
__device__ __nv_bfloat16 g_Wh[G4 * CH];      // W_ih hi split, [g][c]
__device__ __nv_bfloat16 g_Wl[G4 * CH];      // W_ih lo split
__device__ __nv_bfloat16 g_WhhHi[G4 * HID];  // W_hh hi split, [g][k]
__device__ __nv_bfloat16 g_WhhLo[G4 * HID];  // W_hh lo split
__device__ float g_xg[NROW * G4];            // input gates [t*480+seq][g]
__device__ float g_bias[G4];

// ---------------- helpers ----------------
__device__ __forceinline__ float tanh_t(float x) {
    float t; asm("tanh.approx.f32 %0, %1;" : "=f"(t) : "f"(x)); return t;
}
__device__ __forceinline__ uint32_t smem_u32(const void* p) {
    uint32_t a;
    asm("{ .reg .u64 t; cvta.to.shared.u64 t, %1; cvt.u32.u64 %0, t; }" : "=r"(a) : "l"(p));
    return a;
}
__device__ __forceinline__ void mma16816(float* d, const uint32_t* a, uint32_t b0, uint32_t b1) {
    asm volatile(
        "mma.sync.aligned.m16n8k16.row.col.f32.bf16.bf16.f32 "
        "{%0,%1,%2,%3}, {%4,%5,%6,%7}, {%8,%9}, {%0,%1,%2,%3};"
        : "+f"(d[0]), "+f"(d[1]), "+f"(d[2]), "+f"(d[3])
        : "r"(a[0]), "r"(a[1]), "r"(a[2]), "r"(a[3]), "r"(b0), "r"(b1));
}
__device__ __forceinline__ void ldsm4(uint32_t* r, uint32_t addr) {
    asm volatile("ldmatrix.sync.aligned.m8n8.x4.shared.b16 {%0,%1,%2,%3}, [%4];"
        : "=r"(r[0]), "=r"(r[1]), "=r"(r[2]), "=r"(r[3]) : "r"(addr));
}

// ---------------- prep: bf16 splits + bias fold ----------------
__global__ void __launch_bounds__(256) prep_kernel(
    const float* __restrict__ Wih, const float* __restrict__ Whh,
    const float* __restrict__ bih, const float* __restrict__ bhh)
{
    int idx = blockIdx.x * 256 + threadIdx.x;
    if (idx < G4 * HID) {
        float w = Whh[idx];
        __nv_bfloat16 hi = __float2bfloat16(w);
        g_WhhHi[idx] = hi;
        g_WhhLo[idx] = __float2bfloat16(w - __bfloat162float(hi));
    }
    if (idx < G4 * CH) {
        float w = Wih[idx];
        __nv_bfloat16 hi = __float2bfloat16(w);
        g_Wh[idx] = hi;
        g_Wl[idx] = __float2bfloat16(w - __bfloat162float(hi));
    }
    if (idx < G4) g_bias[idx] = bih[idx] + bhh[idx];
}

// ---------------- transpose + bf16 split ----------------
__global__ void __launch_bounds__(256) transp_kernel(const float* __restrict__ x)
{
    __shared__ float tile[64 * 30];
    int t = blockIdx.x, b = blockIdx.y;
    for (int idx = threadIdx.x; idx < 64 * 30; idx += 256) {
        int c = idx / 30, p = idx - c * 30;
        tile[idx] = x[(b * 64 + c) * 6000 + t * 30 + p];
    }
    __syncthreads();
    for (int idx = threadIdx.x; idx < 64 * 30; idx += 256) {
        int p = idx >> 6, c = idx & 63;
        float v = tile[c * 30 + p];
        __nv_bfloat16 hi = __float2bfloat16(v);
        int o = (t * NSEQ + b * 30 + p) * 64 + c;
        g_xh[o] = hi;
        g_xl[o] = __float2bfloat16(v - __bfloat162float(hi));
    }
}

// ---------------- HMMA GEMM: xg = split3(x @ Wih^T) + bias (R9, unchanged) ----------------
#define HG_B0   36864
#define HG_BIAS 73728
#define HG_SMEM 74240

__global__ void __launch_bounds__(256) hgemm_kernel()
{
    extern __shared__ char sm[];
    int tid = threadIdx.x, w = tid >> 5, l = tid & 31;
    int row0 = blockIdx.x * 128, col0 = blockIdx.y * 128;

    for (int i = tid; i < 4096; i += 256) {
        int isB = i >> 11;
        int j = i & 2047;
        int arr = j >> 10, rem = j & 1023, row = rem >> 3, ch = rem & 7;
        const uint4* src;
        size_t gidx;
        if (!isB) {
            src = arr ? (const uint4*)g_xl : (const uint4*)g_xh;
            gidx = (size_t)(row0 + row) * 8 + ch;
        } else {
            src = arr ? (const uint4*)g_Wl : (const uint4*)g_Wh;
            gidx = (size_t)(col0 + row) * 8 + ch;
        }
        *(uint4*)(sm + isB * 36864 + arr * 18432 + row * 144 + ch * 16) = src[gidx];
    }
    if (tid < 128) ((float*)(sm + HG_BIAS))[tid] = g_bias[col0 + tid];
    __syncthreads();

    int lr = l >> 2;
    int lc = (l & 3) * 2;

    float acc[16][4];
#pragma unroll
    for (int nf = 0; nf < 16; nf++)
#pragma unroll
        for (int j = 0; j < 4; j++) acc[nf][j] = 0.f;

#pragma unroll
    for (int kf = 0; kf < 4; kf++) {
        int aoff = (w * 16 + lr) * 144 + (kf * 16 + lc) * 2;
        uint32_t ah[4], al[4];
        ah[0] = *(const uint32_t*)(sm + aoff);
        ah[1] = *(const uint32_t*)(sm + aoff + 8 * 144);
        ah[2] = *(const uint32_t*)(sm + aoff + 16);
        ah[3] = *(const uint32_t*)(sm + aoff + 8 * 144 + 16);
        al[0] = *(const uint32_t*)(sm + 18432 + aoff);
        al[1] = *(const uint32_t*)(sm + 18432 + aoff + 8 * 144);
        al[2] = *(const uint32_t*)(sm + 18432 + aoff + 16);
        al[3] = *(const uint32_t*)(sm + 18432 + aoff + 8 * 144 + 16);
#pragma unroll
        for (int nf = 0; nf < 16; nf++) {
            int boff = HG_B0 + (nf * 8 + lr) * 144 + (kf * 16 + lc) * 2;
            uint32_t bh0 = *(const uint32_t*)(sm + boff);
            uint32_t bh1 = *(const uint32_t*)(sm + boff + 16);
            uint32_t bl0 = *(const uint32_t*)(sm + boff + 18432);
            uint32_t bl1 = *(const uint32_t*)(sm + boff + 18432 + 16);
            mma16816(acc[nf], ah, bh0, bh1);
            mma16816(acc[nf], al, bh0, bh1);
            mma16816(acc[nf], ah, bl0, bl1);
        }
    }

    const float* bs = (const float*)(sm + HG_BIAS);
    int rgA = row0 + w * 16 + lr;
#pragma unroll
    for (int nf = 0; nf < 16; nf++) {
        float b0 = bs[nf * 8 + lc], b1 = bs[nf * 8 + lc + 1];
        size_t cA = (size_t)rgA * 512 + col0 + nf * 8 + lc;
        *(float2*)&g_xg[cA] = make_float2(acc[nf][0] + b0, acc[nf][1] + b1);
        *(float2*)&g_xg[cA + 8 * 512] = make_float2(acc[nf][2] + b0, acc[nf][3] + b1);
    }
}

// ---------------- persistent LSTM: combined-B HMMA, hoisted xb + B pipeline ----------------
// lstm4 (R12 best) + (1) xb gate loads hoisted into registers after the barrier,
// (2) B fragments prefetched one kf ahead (2 regs), single accumulator kept.
// smem:
#define L4_WLO 0                       // WhhLo padded: 512 rows x 272 B = 139264
#define L4_XB  139264                  // xg double buf: 2 x 4x520 floats = 16640
#define L4_HB  155904                  // B double buf: 2 x 8 cols x 272 B = 4352
#define L4_HF  160256                  // h fp32 [128][4] = 2048
#define L4_TOTAL 162304

__global__ void __launch_bounds__(256) lstm8_kernel(
    const float* __restrict__ Wfc, const float* __restrict__ bfc,
    float* __restrict__ out)
{
    extern __shared__ char sm[];
    int tid = threadIdx.x, w = tid >> 5, l = tid & 31;
    int s0 = blockIdx.x * 4;
    uint32_t smb = smem_u32(sm);

    // stage WhhLo into 272-B padded rows
    {
        const uint32_t* wlo = (const uint32_t*)g_WhhLo;  // [512][64] u32
        for (int i = tid; i < 512 * 64; i += 256) {
            int row = i >> 6, cp = i & 63;
            *(uint32_t*)(sm + L4_WLO + row * 272 + cp * 4) = wlo[row * 64 + cp];
        }
    }
    // zero h (B) buffers
    for (int i = tid; i < 4352 / 4; i += 256) ((uint32_t*)(sm + L4_HB))[i] = 0;
    // preload xb t=0 (buffer 0)
    const float4* xg4 = (const float4*)g_xg;
    for (int i = tid; i < 512; i += 256) {
        int s = i >> 7, g4i = i & 127;
        *(float4*)(sm + L4_XB + (s * 520 + g4i * 4) * 4) = xg4[(size_t)(s0 + s) * 128 + g4i];
    }

    // WhhHi fragments -> registers: WH[gate][kf][4], rows gate*128 + w*16
    uint32_t WH[4][8][4];
    {
        const uint32_t* whi = (const uint32_t*)g_WhhHi;  // [512][64] u32
        int lr = l >> 2, lc = l & 3;
#pragma unroll
        for (int mf = 0; mf < 4; mf++)
#pragma unroll
            for (int kf = 0; kf < 8; kf++) {
                int row = mf * 128 + w * 16 + lr;
                int kc = kf * 8 + lc;
                WH[mf][kf][0] = whi[row * 64 + kc];
                WH[mf][kf][1] = whi[(row + 8) * 64 + kc];
                WH[mf][kf][2] = whi[row * 64 + kc + 4];
                WH[mf][kf][3] = whi[(row + 8) * 64 + kc + 4];
            }
    }
    __syncthreads();

    // ldmatrix lane base for WhhLo A-frags (mf stride 128*272)
    int lm = l >> 3, lr8 = l & 7;
    uint32_t wloBase = smb + L4_WLO
        + (uint32_t)((w * 16 + (lm & 1) * 8 + lr8) * 272 + ((lm >> 1) * 8) * 2);

    // register-resident Wlo for mf=0
    uint32_t WL0[8][4];
#pragma unroll
    for (int kf = 0; kf < 8; kf++) ldsm4(WL0[kf], wloBase + kf * 32);

    // B-frag lane base (buffer 0)
    uint32_t hbA = smb + L4_HB + (uint32_t)((l >> 2) * 272 + (l & 3) * 4);

    // xb prefetch mapping
    int rC = tid & 127, sB = tid >> 7;

    // cell ownership: each lane owns (rL, sL) and (rL, sL+1)
    bool Alane = (l & 3) < 2;
    int rL = w * 16 + (l >> 2) + (Alane ? 0 : 8);
    int sL = ((l & 3) & 1) * 2;
    float cs0 = 0.f, cs1 = 0.f;

#pragma unroll 1
    for (int t = 0; t < TLEN; t++) {
        bool pf = (t + 1 < TLEN);
        float4 nx0, nx1;
        if (pf) {
            nx0 = xg4[(size_t)((t + 1) * NSEQ + s0 + sB) * 128 + rC];
            nx1 = xg4[(size_t)((t + 1) * NSEQ + s0 + sB + 2) * 128 + rC];
        }

        // (1) hoist xb gate reads into registers (buffer t is stable post-barrier)
        const float* xbc = (const float*)(sm + L4_XB + (t & 1) * 8320);
        float xr0[4], xr1[4];
#pragma unroll
        for (int mf = 0; mf < 4; mf++) {
            xr0[mf] = xbc[sL * 520 + mf * 128 + rL];
            xr1[mf] = xbc[(sL + 1) * 520 + mf * 128 + rL];
        }

        uint32_t hcur = hbA + (t & 1) * 2176;
        float acc[4][4];
#pragma unroll
        for (int mf = 0; mf < 4; mf++) {
            acc[mf][0] = 0.f; acc[mf][1] = 0.f; acc[mf][2] = 0.f; acc[mf][3] = 0.f;
        }

        // (2) B pipeline: prefetch kf=0, then kf+1 inside the loop
        uint32_t bh0, bh1;
        asm volatile("ld.shared.b32 %0, [%1];" : "=r"(bh0) : "r"(hcur));
        asm volatile("ld.shared.b32 %0, [%1];" : "=r"(bh1) : "r"(hcur + 16));

#pragma unroll
        for (int kf = 0; kf < 8; kf++) {
            uint32_t nbh0 = 0, nbh1 = 0;
            if (kf < 7) {
                uint32_t ka = hcur + (kf + 1) * 32;
                asm volatile("ld.shared.b32 %0, [%1];" : "=r"(nbh0) : "r"(ka));
                asm volatile("ld.shared.b32 %0, [%1];" : "=r"(nbh1) : "r"(ka + 16));
            }
            // mf = 0: both W halves in registers
            mma16816(acc[0], WH[0][kf], bh0, bh1);
            mma16816(acc[0], WL0[kf], bh0, bh1);
#pragma unroll
            for (int mf = 1; mf < 4; mf++) {
                uint32_t wl[4];
                ldsm4(wl, wloBase + mf * (128 * 272) + kf * 32);
                mma16816(acc[mf], WH[mf][kf], bh0, bh1);
                mma16816(acc[mf], wl, bh0, bh1);
            }
            bh0 = nbh0; bh1 = nbh1;
        }

        // store next xb buffer
        if (pf) {
            float* xd = (float*)(sm + L4_XB + ((t + 1) & 1) * 8320);
            *(float4*)&xd[sB * 520 + rC * 4] = nx0;
            *(float4*)&xd[(sB + 2) * 520 + rC * 4] = nx1;
        }

        // half-column sums via shfl_xor(2): lane gets its 2 complete cells
        float g0[4], g1[4];
#pragma unroll
        for (int mf = 0; mf < 4; mf++) {
            float sa = Alane ? acc[mf][2] : acc[mf][0];
            float ra = __shfl_xor_sync(0xffffffffu, sa, 2);
            float sb2 = Alane ? acc[mf][3] : acc[mf][1];
            float rb = __shfl_xor_sync(0xffffffffu, sb2, 2);
            g0[mf] = (Alane ? acc[mf][0] : acc[mf][2]) + ra;
            g1[mf] = (Alane ? acc[mf][1] : acc[mf][3]) + rb;
        }

        // activations: 2 cells per lane (xb already in registers)
        {
            char* hn = sm + L4_HB + ((t + 1) & 1) * 2176;
            float* hf = (float*)(sm + L4_HF);

            // cell 0: (rL, sL)
            {
                float gi = g0[0] + xr0[0];
                float gf = g0[1] + xr0[1];
                float gg = g0[2] + xr0[2];
                float go = g0[3] + xr0[3];
                float i_ = 0.5f * tanh_t(0.5f * gi) + 0.5f;
                float f_ = 0.5f * tanh_t(0.5f * gf) + 0.5f;
                float o_ = 0.5f * tanh_t(0.5f * go) + 0.5f;
                float g_ = tanh_t(gg);
                cs0 = f_ * cs0 + i_ * g_;
                float h = o_ * tanh_t(cs0);
                __nv_bfloat16 hi = __float2bfloat16(h);
                float lo = h - __bfloat162float(hi);
                *(__nv_bfloat16*)(hn + sL * 272 + rL * 2) = hi;
                *(__nv_bfloat16*)(hn + (4 + sL) * 272 + rL * 2) = __float2bfloat16(lo);
                if (t == TLEN - 1) hf[rL * 4 + sL] = h;
            }
            // cell 1: (rL, sL+1)
            {
                int s1 = sL + 1;
                float gi = g1[0] + xr1[0];
                float gf = g1[1] + xr1[1];
                float gg = g1[2] + xr1[2];
                float go = g1[3] + xr1[3];
                float i_ = 0.5f * tanh_t(0.5f * gi) + 0.5f;
                float f_ = 0.5f * tanh_t(0.5f * gf) + 0.5f;
                float o_ = 0.5f * tanh_t(0.5f * go) + 0.5f;
                float g_ = tanh_t(gg);
                cs1 = f_ * cs1 + i_ * g_;
                float h = o_ * tanh_t(cs1);
                __nv_bfloat16 hi = __float2bfloat16(h);
                float lo = h - __bfloat162float(hi);
                *(__nv_bfloat16*)(hn + s1 * 272 + rL * 2) = hi;
                *(__nv_bfloat16*)(hn + (4 + s1) * 272 + rL * 2) = __float2bfloat16(lo);
                if (t == TLEN - 1) hf[rL * 4 + s1] = h;
            }
        }
        __syncthreads();
    }

    // ---- FC epilogue: reuse WLO region for W_fc^T ----
    float* wfs = (float*)sm;
    for (int idx = tid; idx < CH * HID; idx += 256) {
        int c = idx >> 7, j = idx & 127;
        wfs[j * 64 + c] = Wfc[idx];
    }
    __syncthreads();
    {
        int c = tid & 63, s = tid >> 6;
        float accf = bfc[c];
        const float* hf = (const float*)(sm + L4_HF);
#pragma unroll 8
        for (int j = 0; j < HID; j++)
            accf += hf[j * 4 + s] * wfs[j * 64 + c];
        out[(s0 + s) * 64 + c] = accf;
    }
}

// ---------------- launch ----------------
extern "C" void kernel_launch(void* const* d_in, const int* in_sizes, int n_in,
                              void* d_out, int out_size)
{
    const float* x   = (const float*)d_in[0];
    const float* Wih = (const float*)d_in[1];
    const float* Whh = (const float*)d_in[2];
    const float* bih = (const float*)d_in[3];
    const float* bhh = (const float*)d_in[4];
    const float* Wfc = (const float*)d_in[5];
    const float* bfc = (const float*)d_in[6];
    float* out = (float*)d_out;

    cudaFuncSetAttribute(hgemm_kernel, cudaFuncAttributeMaxDynamicSharedMemorySize, HG_SMEM);
    cudaFuncSetAttribute(lstm8_kernel, cudaFuncAttributeMaxDynamicSharedMemorySize, L4_TOTAL);

    prep_kernel<<<256, 256>>>(Wih, Whh, bih, bhh);
    transp_kernel<<<dim3(TLEN, 16), 256>>>(x);
    hgemm_kernel<<<dim3(NROW / 128, 4), 256, HG_SMEM>>>();
    lstm8_kernel<<<120, 256, L4_TOTAL>>>(Wfc, bfc, out);
}

// round 17
// speedup vs baseline: 1.4165x; 1.1166x over previous
#include <cuda_runtime.h>
#include <cuda_bf16.h>
#include <cstdint>

typedef unsigned long long ull;

#define NSEQ 480
#define TLEN 200
#define CH   64
#define HID  128
#define G4   512
#define NROW (NSEQ * TLEN)   // 96000

// ---------------- device scratch ----------------
__device__ __nv_bfloat16 g_xh[NROW * CH];    // x hi split, [t*480+seq][c]
__device__ __nv_bfloat16 g_xl[NROW * CH];    // x lo split
__device__ __nv_bfloat16 g_Wh[G4 * CH];      // W_ih hi split, [g][c]
__device__ __nv_bfloat16 g_Wl[G4 * CH];      // W_ih lo split
__device__ __nv_bfloat16 g_WhhHi[G4 * HID];  // W_hh hi split, [g][k]
__device__ __nv_bfloat16 g_WhhLo[G4 * HID];  // W_hh lo split
__device__ float g_xg[NROW * G4];            // input gates [t*480+seq][g]
__device__ float g_bias[G4];

// ---------------- helpers ----------------
__device__ __forceinline__ float tanh_t(float x) {
    float t; asm("tanh.approx.f32 %0, %1;" : "=f"(t) : "f"(x)); return t;
}
__device__ __forceinline__ uint32_t smem_u32(const void* p) {
    uint32_t a;
    asm("{ .reg .u64 t; cvta.to.shared.u64 t, %1; cvt.u32.u64 %0, t; }" : "=r"(a) : "l"(p));
    return a;
}
__device__ __forceinline__ void mma16816(float* d, const uint32_t* a, uint32_t b0, uint32_t b1) {
    asm volatile(
        "mma.sync.aligned.m16n8k16.row.col.f32.bf16.bf16.f32 "
        "{%0,%1,%2,%3}, {%4,%5,%6,%7}, {%8,%9}, {%0,%1,%2,%3};"
        : "+f"(d[0]), "+f"(d[1]), "+f"(d[2]), "+f"(d[3])
        : "r"(a[0]), "r"(a[1]), "r"(a[2]), "r"(a[3]), "r"(b0), "r"(b1));
}
__device__ __forceinline__ void ldsm4(uint32_t* r, uint32_t addr) {
    asm volatile("ldmatrix.sync.aligned.m8n8.x4.shared.b16 {%0,%1,%2,%3}, [%4];"
        : "=r"(r[0]), "=r"(r[1]), "=r"(r[2]), "=r"(r[3]) : "r"(addr));
}

// ---------------- prep: bf16 splits + bias fold ----------------
__global__ void __launch_bounds__(256) prep_kernel(
    const float* __restrict__ Wih, const float* __restrict__ Whh,
    const float* __restrict__ bih, const float* __restrict__ bhh)
{
    int idx = blockIdx.x * 256 + threadIdx.x;
    if (idx < G4 * HID) {
        float w = Whh[idx];
        __nv_bfloat16 hi = __float2bfloat16(w);
        g_WhhHi[idx] = hi;
        g_WhhLo[idx] = __float2bfloat16(w - __bfloat162float(hi));
    }
    if (idx < G4 * CH) {
        float w = Wih[idx];
        __nv_bfloat16 hi = __float2bfloat16(w);
        g_Wh[idx] = hi;
        g_Wl[idx] = __float2bfloat16(w - __bfloat162float(hi));
    }
    if (idx < G4) g_bias[idx] = bih[idx] + bhh[idx];
}

// ---------------- transpose + bf16 split ----------------
__global__ void __launch_bounds__(256) transp_kernel(const float* __restrict__ x)
{
    __shared__ float tile[64 * 30];
    int t = blockIdx.x, b = blockIdx.y;
    for (int idx = threadIdx.x; idx < 64 * 30; idx += 256) {
        int c = idx / 30, p = idx - c * 30;
        tile[idx] = x[(b * 64 + c) * 6000 + t * 30 + p];
    }
    __syncthreads();
    for (int idx = threadIdx.x; idx < 64 * 30; idx += 256) {
        int p = idx >> 6, c = idx & 63;
        float v = tile[c * 30 + p];
        __nv_bfloat16 hi = __float2bfloat16(v);
        int o = (t * NSEQ + b * 30 + p) * 64 + c;
        g_xh[o] = hi;
        g_xl[o] = __float2bfloat16(v - __bfloat162float(hi));
    }
}

// ---------------- HMMA GEMM with A-reuse: grid 750, inner loop over 4 col tiles ----------------
// smem: A (xh,xl) 2x128x144; B (Wh,Wl) 2x128x144; bias 512 floats
#define HG_B0   36864
#define HG_BIAS 73728
#define HG_SMEM 75776

__global__ void __launch_bounds__(256) hgemm_kernel()
{
    extern __shared__ char sm[];
    int tid = threadIdx.x, w = tid >> 5, l = tid & 31;
    int row0 = blockIdx.x * 128;

    // stage A tiles once
    for (int i = tid; i < 2048; i += 256) {
        int arr = i >> 10, rem = i & 1023, row = rem >> 3, ch = rem & 7;
        const uint4* src = arr ? (const uint4*)g_xl : (const uint4*)g_xh;
        *(uint4*)(sm + arr * 18432 + row * 144 + ch * 16) = src[(size_t)(row0 + row) * 8 + ch];
    }
    // stage full bias
    for (int i = tid; i < 512; i += 256) ((float*)(sm + HG_BIAS))[i] = g_bias[i];

    int lr = l >> 2;
    int lc = (l & 3) * 2;

    for (int cb = 0; cb < 4; cb++) {
        int col0 = cb * 128;
        // stage B tiles for this column chunk
        for (int i = tid; i < 2048; i += 256) {
            int arr = i >> 10, rem = i & 1023, row = rem >> 3, ch = rem & 7;
            const uint4* src = arr ? (const uint4*)g_Wl : (const uint4*)g_Wh;
            *(uint4*)(sm + HG_B0 + arr * 18432 + row * 144 + ch * 16) =
                src[(size_t)(col0 + row) * 8 + ch];
        }
        __syncthreads();

        float acc[16][4];
#pragma unroll
        for (int nf = 0; nf < 16; nf++)
#pragma unroll
            for (int j = 0; j < 4; j++) acc[nf][j] = 0.f;

#pragma unroll
        for (int kf = 0; kf < 4; kf++) {
            int aoff = (w * 16 + lr) * 144 + (kf * 16 + lc) * 2;
            uint32_t ah[4], al[4];
            ah[0] = *(const uint32_t*)(sm + aoff);
            ah[1] = *(const uint32_t*)(sm + aoff + 8 * 144);
            ah[2] = *(const uint32_t*)(sm + aoff + 16);
            ah[3] = *(const uint32_t*)(sm + aoff + 8 * 144 + 16);
            al[0] = *(const uint32_t*)(sm + 18432 + aoff);
            al[1] = *(const uint32_t*)(sm + 18432 + aoff + 8 * 144);
            al[2] = *(const uint32_t*)(sm + 18432 + aoff + 16);
            al[3] = *(const uint32_t*)(sm + 18432 + aoff + 8 * 144 + 16);
#pragma unroll
            for (int nf = 0; nf < 16; nf++) {
                int boff = HG_B0 + (nf * 8 + lr) * 144 + (kf * 16 + lc) * 2;
                uint32_t bh0 = *(const uint32_t*)(sm + boff);
                uint32_t bh1 = *(const uint32_t*)(sm + boff + 16);
                uint32_t bl0 = *(const uint32_t*)(sm + boff + 18432);
                uint32_t bl1 = *(const uint32_t*)(sm + boff + 18432 + 16);
                mma16816(acc[nf], ah, bh0, bh1);
                mma16816(acc[nf], al, bh0, bh1);
                mma16816(acc[nf], ah, bl0, bl1);
            }
        }

        const float* bs = (const float*)(sm + HG_BIAS);
        int rgA = row0 + w * 16 + lr;
#pragma unroll
        for (int nf = 0; nf < 16; nf++) {
            float b0 = bs[col0 + nf * 8 + lc], b1 = bs[col0 + nf * 8 + lc + 1];
            size_t cA = (size_t)rgA * 512 + col0 + nf * 8 + lc;
            *(float2*)&g_xg[cA] = make_float2(acc[nf][0] + b0, acc[nf][1] + b1);
            *(float2*)&g_xg[cA + 8 * 512] = make_float2(acc[nf][2] + b0, acc[nf][3] + b1);
        }
        __syncthreads();   // all warps done with B before restaging
    }
}

// ---------------- persistent LSTM: lstm8 + cross-step Wlo kf=0 prefetch ----------------
#define L4_WLO 0                       // WhhLo padded: 512 rows x 272 B = 139264
#define L4_XB  139264                  // xg double buf: 2 x 4x520 floats = 16640
#define L4_HB  155904                  // B double buf: 2 x 8 cols x 272 B = 4352
#define L4_HF  160256                  // h fp32 [128][4] = 2048
#define L4_TOTAL 162304

__global__ void __launch_bounds__(256) lstm9_kernel(
    const float* __restrict__ Wfc, const float* __restrict__ bfc,
    float* __restrict__ out)
{
    extern __shared__ char sm[];
    int tid = threadIdx.x, w = tid >> 5, l = tid & 31;
    int s0 = blockIdx.x * 4;
    uint32_t smb = smem_u32(sm);

    // stage WhhLo into 272-B padded rows
    {
        const uint32_t* wlo = (const uint32_t*)g_WhhLo;  // [512][64] u32
        for (int i = tid; i < 512 * 64; i += 256) {
            int row = i >> 6, cp = i & 63;
            *(uint32_t*)(sm + L4_WLO + row * 272 + cp * 4) = wlo[row * 64 + cp];
        }
    }
    // zero h (B) buffers
    for (int i = tid; i < 4352 / 4; i += 256) ((uint32_t*)(sm + L4_HB))[i] = 0;
    // preload xb t=0 (buffer 0)
    const float4* xg4 = (const float4*)g_xg;
    for (int i = tid; i < 512; i += 256) {
        int s = i >> 7, g4i = i & 127;
        *(float4*)(sm + L4_XB + (s * 520 + g4i * 4) * 4) = xg4[(size_t)(s0 + s) * 128 + g4i];
    }

    // WhhHi fragments -> registers: WH[gate][kf][4], rows gate*128 + w*16
    uint32_t WH[4][8][4];
    {
        const uint32_t* whi = (const uint32_t*)g_WhhHi;  // [512][64] u32
        int lr = l >> 2, lc = l & 3;
#pragma unroll
        for (int mf = 0; mf < 4; mf++)
#pragma unroll
            for (int kf = 0; kf < 8; kf++) {
                int row = mf * 128 + w * 16 + lr;
                int kc = kf * 8 + lc;
                WH[mf][kf][0] = whi[row * 64 + kc];
                WH[mf][kf][1] = whi[(row + 8) * 64 + kc];
                WH[mf][kf][2] = whi[row * 64 + kc + 4];
                WH[mf][kf][3] = whi[(row + 8) * 64 + kc + 4];
            }
    }
    __syncthreads();

    // ldmatrix lane base for WhhLo A-frags (mf stride 128*272)
    int lm = l >> 3, lr8 = l & 7;
    uint32_t wloBase = smb + L4_WLO
        + (uint32_t)((w * 16 + (lm & 1) * 8 + lr8) * 272 + ((lm >> 1) * 8) * 2);

    // register-resident Wlo for mf=0
    uint32_t WL0[8][4];
#pragma unroll
    for (int kf = 0; kf < 8; kf++) ldsm4(WL0[kf], wloBase + kf * 32);

    // cross-step prefetch of Wlo kf=0 fragments (mf=1..3)
    uint32_t wlP[3][4];
#pragma unroll
    for (int m = 0; m < 3; m++) ldsm4(wlP[m], wloBase + (m + 1) * (128 * 272));

    // B-frag lane base (buffer 0)
    uint32_t hbA = smb + L4_HB + (uint32_t)((l >> 2) * 272 + (l & 3) * 4);

    // xb prefetch mapping
    int rC = tid & 127, sB = tid >> 7;

    // cell ownership: each lane owns (rL, sL) and (rL, sL+1)
    bool Alane = (l & 3) < 2;
    int rL = w * 16 + (l >> 2) + (Alane ? 0 : 8);
    int sL = ((l & 3) & 1) * 2;
    float cs0 = 0.f, cs1 = 0.f;

#pragma unroll 1
    for (int t = 0; t < TLEN; t++) {
        bool pf = (t + 1 < TLEN);
        float4 nx0, nx1;
        if (pf) {
            nx0 = xg4[(size_t)((t + 1) * NSEQ + s0 + sB) * 128 + rC];
            nx1 = xg4[(size_t)((t + 1) * NSEQ + s0 + sB + 2) * 128 + rC];
        }

        // hoist xb gate reads into registers (buffer t stable post-barrier)
        const float* xbc = (const float*)(sm + L4_XB + (t & 1) * 8320);
        float xr0[4], xr1[4];
#pragma unroll
        for (int mf = 0; mf < 4; mf++) {
            xr0[mf] = xbc[sL * 520 + mf * 128 + rL];
            xr1[mf] = xbc[(sL + 1) * 520 + mf * 128 + rL];
        }

        uint32_t hcur = hbA + (t & 1) * 2176;
        float acc[4][4];
#pragma unroll
        for (int mf = 0; mf < 4; mf++) {
            acc[mf][0] = 0.f; acc[mf][1] = 0.f; acc[mf][2] = 0.f; acc[mf][3] = 0.f;
        }

        // B pipeline: prefetch kf=0, then kf+1 inside the loop
        uint32_t bh0, bh1;
        asm volatile("ld.shared.b32 %0, [%1];" : "=r"(bh0) : "r"(hcur));
        asm volatile("ld.shared.b32 %0, [%1];" : "=r"(bh1) : "r"(hcur + 16));

#pragma unroll
        for (int kf = 0; kf < 8; kf++) {
            uint32_t nbh0 = 0, nbh1 = 0;
            if (kf < 7) {
                uint32_t ka = hcur + (kf + 1) * 32;
                asm volatile("ld.shared.b32 %0, [%1];" : "=r"(nbh0) : "r"(ka));
                asm volatile("ld.shared.b32 %0, [%1];" : "=r"(nbh1) : "r"(ka + 16));
            }
            // mf = 0: both W halves in registers
            mma16816(acc[0], WH[0][kf], bh0, bh1);
            mma16816(acc[0], WL0[kf], bh0, bh1);
            if (kf == 0) {
                // use cross-step prefetched Wlo fragments
#pragma unroll
                for (int mf = 1; mf < 4; mf++) {
                    mma16816(acc[mf], WH[mf][0], bh0, bh1);
                    mma16816(acc[mf], wlP[mf - 1], bh0, bh1);
                }
            } else {
#pragma unroll
                for (int mf = 1; mf < 4; mf++) {
                    uint32_t wl[4];
                    ldsm4(wl, wloBase + mf * (128 * 272) + kf * 32);
                    mma16816(acc[mf], WH[mf][kf], bh0, bh1);
                    mma16816(acc[mf], wl, bh0, bh1);
                }
            }
            bh0 = nbh0; bh1 = nbh1;
        }

        // re-prefetch kf=0 Wlo fragments for the NEXT step (no barrier dependency)
#pragma unroll
        for (int m = 0; m < 3; m++) ldsm4(wlP[m], wloBase + (m + 1) * (128 * 272));

        // store next xb buffer
        if (pf) {
            float* xd = (float*)(sm + L4_XB + ((t + 1) & 1) * 8320);
            *(float4*)&xd[sB * 520 + rC * 4] = nx0;
            *(float4*)&xd[(sB + 2) * 520 + rC * 4] = nx1;
        }

        // half-column sums via shfl_xor(2): lane gets its 2 complete cells
        float g0[4], g1[4];
#pragma unroll
        for (int mf = 0; mf < 4; mf++) {
            float sa = Alane ? acc[mf][2] : acc[mf][0];
            float ra = __shfl_xor_sync(0xffffffffu, sa, 2);
            float sb2 = Alane ? acc[mf][3] : acc[mf][1];
            float rb = __shfl_xor_sync(0xffffffffu, sb2, 2);
            g0[mf] = (Alane ? acc[mf][0] : acc[mf][2]) + ra;
            g1[mf] = (Alane ? acc[mf][1] : acc[mf][3]) + rb;
        }

        // activations: 2 cells per lane (xb already in registers)
        {
            char* hn = sm + L4_HB + ((t + 1) & 1) * 2176;
            float* hf = (float*)(sm + L4_HF);

            // cell 0: (rL, sL)
            {
                float gi = g0[0] + xr0[0];
                float gf = g0[1] + xr0[1];
                float gg = g0[2] + xr0[2];
                float go = g0[3] + xr0[3];
                float i_ = 0.5f * tanh_t(0.5f * gi) + 0.5f;
                float f_ = 0.5f * tanh_t(0.5f * gf) + 0.5f;
                float o_ = 0.5f * tanh_t(0.5f * go) + 0.5f;
                float g_ = tanh_t(gg);
                cs0 = f_ * cs0 + i_ * g_;
                float h = o_ * tanh_t(cs0);
                __nv_bfloat16 hi = __float2bfloat16(h);
                float lo = h - __bfloat162float(hi);
                *(__nv_bfloat16*)(hn + sL * 272 + rL * 2) = hi;
                *(__nv_bfloat16*)(hn + (4 + sL) * 272 + rL * 2) = __float2bfloat16(lo);
                if (t == TLEN - 1) hf[rL * 4 + sL] = h;
            }
            // cell 1: (rL, sL+1)
            {
                int s1 = sL + 1;
                float gi = g1[0] + xr1[0];
                float gf = g1[1] + xr1[1];
                float gg = g1[2] + xr1[2];
                float go = g1[3] + xr1[3];
                float i_ = 0.5f * tanh_t(0.5f * gi) + 0.5f;
                float f_ = 0.5f * tanh_t(0.5f * gf) + 0.5f;
                float o_ = 0.5f * tanh_t(0.5f * go) + 0.5f;
                float g_ = tanh_t(gg);
                cs1 = f_ * cs1 + i_ * g_;
                float h = o_ * tanh_t(cs1);
                __nv_bfloat16 hi = __float2bfloat16(h);
                float lo = h - __bfloat162float(hi);
                *(__nv_bfloat16*)(hn + s1 * 272 + rL * 2) = hi;
                *(__nv_bfloat16*)(hn + (4 + s1) * 272 + rL * 2) = __float2bfloat16(lo);
                if (t == TLEN - 1) hf[rL * 4 + s1] = h;
            }
        }
        __syncthreads();
    }

    // ---- FC epilogue: reuse WLO region for W_fc^T ----
    float* wfs = (float*)sm;
    for (int idx = tid; idx < CH * HID; idx += 256) {
        int c = idx >> 7, j = idx & 127;
        wfs[j * 64 + c] = Wfc[idx];
    }
    __syncthreads();
    {
        int c = tid & 63, s = tid >> 6;
        float accf = bfc[c];
        const float* hf = (const float*)(sm + L4_HF);
#pragma unroll 8
        for (int j = 0; j < HID; j++)
            accf += hf[j * 4 + s] * wfs[j * 64 + c];
        out[(s0 + s) * 64 + c] = accf;
    }
}

// ---------------- launch ----------------
extern "C" void kernel_launch(void* const* d_in, const int* in_sizes, int n_in,
                              void* d_out, int out_size)
{
    const float* x   = (const float*)d_in[0];
    const float* Wih = (const float*)d_in[1];
    const float* Whh = (const float*)d_in[2];
    const float* bih = (const float*)d_in[3];
    const float* bhh = (const float*)d_in[4];
    const float* Wfc = (const float*)d_in[5];
    const float* bfc = (const float*)d_in[6];
    float* out = (float*)d_out;

    cudaFuncSetAttribute(hgemm_kernel, cudaFuncAttributeMaxDynamicSharedMemorySize, HG_SMEM);
    cudaFuncSetAttribute(lstm9_kernel, cudaFuncAttributeMaxDynamicSharedMemorySize, L4_TOTAL);

    prep_kernel<<<256, 256>>>(Wih, Whh, bih, bhh);
    transp_kernel<<<dim3(TLEN, 16), 256>>>(x);
    hgemm_kernel<<<NROW / 128, 256, HG_SMEM>>>();
    lstm9_kernel<<<120, 256, L4_TOTAL>>>(Wfc, bfc, out);
}